// round 13
// baseline (speedup 1.0000x reference)
#include <cuda_runtime.h>
#include <cstdint>

#define G 1024
#define BATCH 4
#define TILE_R 10
#define NCHUNK 103               // 102*10 + 3 = 1023 quad rows
#define NBLOCKS (BATCH * NCHUNK) // 412 CTAs -> one wave @ 3 CTA/SM
#define ROWWORDS 3072            // 1024 vertices * 3 floats
#define SLOTW 3076               // +4 pad words (zeroed; col-1024 reads land here)
#define NSLOT 6
#define BSTRIDE (G * G * 3)
#define SMEM_BYTES (NSLOT * SLOTW * 4)   // 73,824 B

// E = 1023*1023 + 1022*1023 + 1023*1022 = 3,137,541 ; N = B*E
#define N_TOTAL 12550164.0

__device__ double g_acc = 0.0;
__device__ unsigned int g_done = 0;

struct V3 { float x, y, z; };

__device__ __forceinline__ V3 vsub(V3 a, V3 b) {
    V3 r; r.x = a.x - b.x; r.y = a.y - b.y; r.z = a.z - b.z; return r;
}
__device__ __forceinline__ V3 vcross(V3 a, V3 b) {
    V3 r;
    r.x = fmaf(a.y, b.z, -a.z * b.y);
    r.y = fmaf(a.z, b.x, -a.x * b.z);
    r.z = fmaf(a.x, b.y, -a.y * b.x);
    return r;
}
__device__ __forceinline__ float vdot(V3 a, V3 b) {
    return fmaf(a.x, b.x, fmaf(a.y, b.y, a.z * b.z));
}
__device__ __forceinline__ float rq(V3 a) {            // rsqrt(max(|a|^2, eps^2))
    return rsqrtf(fmaxf(vdot(a, a), 1e-16f));
}
__device__ __forceinline__ V3 vscale(V3 a, float s) {
    V3 r; r.x = a.x * s; r.y = a.y * s; r.z = a.z * s; return r;
}

extern __shared__ float sm[];

__global__ void __launch_bounds__(256, 3)
nc_fused_kernel(const float* __restrict__ x, float* __restrict__ out,
                unsigned int nblocks) {
    const int t     = threadIdx.x;
    const int chunk = blockIdx.x % NCHUNK;
    const int bb    = blockIdx.x / NCHUNK;
    const int r0    = chunk * TILE_R;
    const int nr    = min(TILE_R, (G - 1) - r0);

    const float* __restrict__ bbase = x + (size_t)bb * BSTRIDE;

    // zero the pad words of every slot (read only by t==255, masked contributions)
    if (t < NSLOT * 4)
        sm[(t >> 2) * SLOTW + ROWWORDS + (t & 3)] = 0.0f;

    // issue group i: vertex row clamp(r0-1+i) -> slot i%NSLOT (48 B per thread)
    auto issue = [&](int i) {
        int vr = min(max(r0 - 1 + i, 0), G - 1);
        const float* src = bbase + (size_t)vr * ROWWORDS + 12 * t;
        uint32_t dst = (uint32_t)__cvta_generic_to_shared(&sm[(i % NSLOT) * SLOTW + 12 * t]);
        asm volatile(
            "cp.async.cg.shared.global [%0], [%1], 16;\n"
            "cp.async.cg.shared.global [%2], [%3], 16;\n"
            "cp.async.cg.shared.global [%4], [%5], 16;\n"
            "cp.async.commit_group;\n"
            :: "r"(dst), "l"(src), "r"(dst + 16), "l"(src + 4),
               "r"(dst + 32), "l"(src + 8) : "memory");
    };

    issue(0); issue(1); issue(2); issue(3);
    asm volatile("cp.async.wait_group 2;\n" ::: "memory");   // rows r0-1, r0 ready
    __syncthreads();

    // masks
    const float mq[4] = {1.f, 1.f, 1.f, (t == 255) ? 0.f : 1.f};  // quad 4t+q valid
    const float mv0   = (t >= 1) ? 1.f : 0.f;                     // boundary vertical exists
    const int   wm1   = 3 * max(4 * t - 1, 0);                    // col 4t-1 word (clamped)

    // prologue: u2 of quad row r0-1 (rows r0-1 in slot0, r0 in slot1).
    // If r0==0 both slots hold row 0 -> e2 = 0 -> u2p = 0 (horiz auto-masked).
    V3 u2p[4];
    {
        const float* s0 = sm;            // slot 0
        const float* s1 = sm + SLOTW;    // slot 1
        float4 A0 = *(const float4*)(s0 + 12 * t);
        float4 A1 = *(const float4*)(s0 + 12 * t + 4);
        float4 A2 = *(const float4*)(s0 + 12 * t + 8);
        float4 A3 = *(const float4*)(s0 + 12 * t + 12);
        float4 B0 = *(const float4*)(s1 + 12 * t);
        float4 B1 = *(const float4*)(s1 + 12 * t + 4);
        float4 B2 = *(const float4*)(s1 + 12 * t + 8);
        float4 B3 = *(const float4*)(s1 + 12 * t + 12);
        V3 pv[5] = { {A0.x,A0.y,A0.z},{A0.w,A1.x,A1.y},{A1.z,A1.w,A2.x},
                     {A2.y,A2.z,A2.w},{A3.x,A3.y,A3.z} };
        V3 cv[5] = { {B0.x,B0.y,B0.z},{B0.w,B1.x,B1.y},{B1.z,B1.w,B2.x},
                     {B2.y,B2.z,B2.w},{B3.x,B3.y,B3.z} };
        #pragma unroll
        for (int q = 0; q < 4; ++q) {
            V3 e2 = vsub(cv[q],     pv[q]);
            V3 dd = vsub(cv[q + 1], pv[q]);
            V3 cB = vcross(e2, dd);
            u2p[q] = vscale(cB, rq(cB));
        }
    }

    float sum = 0.0f;
    #pragma unroll 1
    for (int it = 0; it < nr; ++it) {
        issue(it + 4);
        asm volatile("cp.async.wait_group 2;\n" ::: "memory");  // row r0+it+1 ready
        __syncthreads();

        const float* cur = sm + ((it + 1) % NSLOT) * SLOTW;     // vertex row r0+it
        const float* nxt = sm + ((it + 2) % NSLOT) * SLOTW;     // vertex row r0+it+1

        float4 A0 = *(const float4*)(cur + 12 * t);
        float4 A1 = *(const float4*)(cur + 12 * t + 4);
        float4 A2 = *(const float4*)(cur + 12 * t + 8);
        float4 A3 = *(const float4*)(cur + 12 * t + 12);
        float4 B0 = *(const float4*)(nxt + 12 * t);
        float4 B1 = *(const float4*)(nxt + 12 * t + 4);
        float4 B2 = *(const float4*)(nxt + 12 * t + 8);
        float4 B3 = *(const float4*)(nxt + 12 * t + 12);
        V3 cv[5] = { {A0.x,A0.y,A0.z},{A0.w,A1.x,A1.y},{A1.z,A1.w,A2.x},
                     {A2.y,A2.z,A2.w},{A3.x,A3.y,A3.z} };
        V3 nv[5] = { {B0.x,B0.y,B0.z},{B0.w,B1.x,B1.y},{B1.z,B1.w,B2.x},
                     {B2.y,B2.z,B2.w},{B3.x,B3.y,B3.z} };
        V3 cm1 = { cur[wm1], cur[wm1 + 1], cur[wm1 + 2] };      // col 4t-1 (clamped)

        // left-neighbor quad's T1 unit normal (for the vertical edge at c=4t)
        V3 e1m = vsub(cv[0], cm1);
        V3 dm  = vsub(nv[0], cm1);
        V3 cM  = vcross(dm, e1m);
        V3 u1m = vscale(cM, rq(cM));   // t==0: e1m=0 -> u1m=0 (masked anyway)

        V3 u1prev = u1m;
        #pragma unroll
        for (int q = 0; q < 4; ++q) {
            V3 e1 = vsub(cv[q + 1], cv[q]);
            V3 e2 = vsub(nv[q],     cv[q]);
            V3 dd = vsub(nv[q + 1], cv[q]);
            V3 cA = vcross(dd, e1);          // T1 normal
            V3 cB = vcross(e2, dd);          // T2 normal
            V3 u1 = vscale(cA, rq(cA));
            V3 u2 = vscale(cB, rq(cB));

            // diag + horiz (u2p==0 on global row 0)
            sum = fmaf(mq[q], vdot(u1, u2) + vdot(u1, u2p[q]), sum);
            // vertical edge at c=4t+q against left quad's u1
            float mvq = (q == 0) ? mv0 : mq[q];
            sum = fmaf(mvq, vdot(u2, u1prev), sum);

            u2p[q] = u2;
            u1prev = u1;
        }
    }

    asm volatile("cp.async.wait_group 0;\n" ::: "memory");   // drain leftover copies

    // ---- block reduction (8 warps) ----
    const int lane = t & 31;
    const int wid  = t >> 5;
    #pragma unroll
    for (int off = 16; off > 0; off >>= 1)
        sum += __shfl_down_sync(0xFFFFFFFFu, sum, off);

    __shared__ float warp_sums[8];
    if (lane == 0) warp_sums[wid] = sum;
    __syncthreads();

    __shared__ bool is_last;
    if (wid == 0) {
        float sv = (lane < 8) ? warp_sums[lane] : 0.0f;
        #pragma unroll
        for (int off = 4; off > 0; off >>= 1)
            sv += __shfl_down_sync(0xFFFFFFFFu, sv, off);
        if (lane == 0) {
            atomicAdd(&g_acc, (double)sv);
            __threadfence();
            unsigned int done = atomicInc(&g_done, nblocks - 1);
            is_last = (done == nblocks - 1);
        }
    }
    __syncthreads();

    if (is_last && t == 0) {
        double acc = atomicAdd(&g_acc, 0.0);      // coherent read
        out[0] = (float)(1.0 - acc / N_TOTAL);    // loss = 1 - mean(cos)
        __threadfence();
        g_acc = 0.0;                               // g_done wrapped via atomicInc
    }
}

extern "C" void kernel_launch(void* const* d_in, const int* in_sizes, int n_in,
                              void* d_out, int out_size) {
    const float* x = (const float*)d_in[0];
    float* out = (float*)d_out;

    cudaFuncSetAttribute(nc_fused_kernel,
                         cudaFuncAttributeMaxDynamicSharedMemorySize, SMEM_BYTES);

    dim3 block(256, 1, 1);
    dim3 grid(NBLOCKS, 1, 1);   // 412 CTAs -> one wave @ 3 CTA/SM
    nc_fused_kernel<<<grid, block, SMEM_BYTES>>>(x, out, NBLOCKS);
}

// round 14
// speedup vs baseline: 1.4037x; 1.4037x over previous
#include <cuda_runtime.h>

#define G 1024
#define BATCH 4
#define ROWS 24
#define NCHUNK 43              // 42*24=1008, last chunk 15 rows (1023 total)
#define NSTRIP 33              // 33 warps * 31 quads = 1023 columns
#define ROWSTRIDE (G * 3)
#define TOTWARPS (NSTRIP * NCHUNK * BATCH)   // 5676
#define NBLOCKS ((TOTWARPS + 7) / 8)         // 710

// E = 1023*1023 + 1022*1023 + 1023*1022 = 3,137,541 ; N = B*E
#define N_TOTAL 12550164.0

__device__ double g_acc = 0.0;
__device__ unsigned int g_done = 0;

struct V3 { float x, y, z; };

__device__ __forceinline__ V3 vsub(V3 a, V3 b) {
    V3 r; r.x = a.x - b.x; r.y = a.y - b.y; r.z = a.z - b.z; return r;
}
__device__ __forceinline__ V3 vadd(V3 a, V3 b) {
    V3 r; r.x = a.x + b.x; r.y = a.y + b.y; r.z = a.z + b.z; return r;
}
__device__ __forceinline__ V3 vcross(V3 a, V3 b) {
    V3 r;
    r.x = fmaf(a.y, b.z, -a.z * b.y);
    r.y = fmaf(a.z, b.x, -a.x * b.z);
    r.z = fmaf(a.x, b.y, -a.y * b.x);
    return r;
}
__device__ __forceinline__ float vdot(V3 a, V3 b) {
    return fmaf(a.x, b.x, fmaf(a.y, b.y, a.z * b.z));
}
__device__ __forceinline__ float rq(V3 a) {            // rsqrt(max(|a|^2, eps^2))
    return rsqrtf(fmaxf(vdot(a, a), 1e-16f));
}
__device__ __forceinline__ V3 vscale(V3 a, float s) {
    V3 r; r.x = a.x * s; r.y = a.y * s; r.z = a.z * s; return r;
}
__device__ __forceinline__ V3 ldv(const float* __restrict__ p) {
    V3 r; r.x = p[0]; r.y = p[1]; r.z = p[2]; return r;
}
__device__ __forceinline__ V3 shup(V3 v) {
    V3 r;
    r.x = __shfl_up_sync(0xFFFFFFFFu, v.x, 1);
    r.y = __shfl_up_sync(0xFFFFFFFFu, v.y, 1);
    r.z = __shfl_up_sync(0xFFFFFFFFu, v.z, 1);
    return r;
}
__device__ __forceinline__ V3 shdn(V3 v) {
    V3 r;
    r.x = __shfl_down_sync(0xFFFFFFFFu, v.x, 1);
    r.y = __shfl_down_sync(0xFFFFFFFFu, v.y, 1);
    r.z = __shfl_down_sync(0xFFFFFFFFu, v.z, 1);
    return r;
}

struct St {
    const float* row;      // points at column c of current vertex row
    V3 p00, p01, u2prev;
    float m_dh, m_v;
    bool  tail;            // lane 31: needs explicit p11 load
    int   d3;              // 3 if col c+1 exists else 0 (lane-31 clamp)
};

__device__ __forceinline__ float quad_row(St& s) {
    const float* __restrict__ nrow = s.row + ROWSTRIDE;
    V3 p10 = ldv(nrow);
    // p11 = next lane's p10; lane 31 loads the boundary column explicitly (1 wavefront)
    V3 p11 = shdn(p10);
    if (s.tail) p11 = ldv(nrow + s.d3);

    V3 e1 = vsub(s.p01, s.p00);
    V3 e2 = vsub(p10,  s.p00);
    V3 dd = vsub(p11,  s.p00);

    V3 cA = vcross(dd, e1);          // T1 normal (tl,br,tr)
    V3 cB = vcross(e2, dd);          // T2 normal (tl,bl,br)
    V3 u1 = vscale(cA, rq(cA));
    V3 u2 = vscale(cB, rq(cB));

    // diag + horiz fused: dot(u1,u2) + dot(u1,u2prev) = dot(u1, u2+u2prev)
    float acc = s.m_dh * vdot(u1, vadd(u2, s.u2prev));
    // vert: left quad's u1 via shuffle
    V3 u1l = shup(u1);
    acc = fmaf(s.m_v, vdot(u2, u1l), acc);

    s.p00 = p10; s.p01 = p11; s.u2prev = u2; s.row = nrow;
    return acc;
}

__global__ void __launch_bounds__(256, 5)
nc_fused_kernel(const float* __restrict__ x, float* __restrict__ out,
                unsigned int nblocks) {
    const int lane = threadIdx.x & 31;
    const int wid  = threadIdx.x >> 5;
    const int W    = blockIdx.x * 8 + wid;

    float sum = 0.0f;
    if (W < TOTWARPS) {
        const int strip = W % NSTRIP;
        const int rest  = W / NSTRIP;
        const int chunk = rest % NCHUNK;
        const int bb    = rest / NCHUNK;

        const int c  = strip * 31 + lane;       // 0..1023
        const int r0 = chunk * ROWS;
        const bool cvalid = (c < G - 1);        // c <= 1022

        St s;
        s.tail = (lane == 31);
        s.d3   = cvalid ? 3 : 0;
        s.m_dh = (lane < 31) ? 1.0f : 0.0f;     // diag+horiz owner lanes
        s.m_v  = (lane >= 1 && cvalid) ? 1.0f : 0.0f;

        const float* __restrict__ base = x + (size_t)bb * (size_t)G * G * 3;
        s.row = base + ((size_t)r0 * G + c) * 3;
        s.p00 = ldv(s.row);
        s.p01 = shdn(s.p00);
        if (s.tail) s.p01 = ldv(s.row + s.d3);
        s.u2prev = V3{0.f, 0.f, 0.f};
        if (r0 >= 1) {                           // û2 of quad (r0-1, c)
            V3 pm = ldv(s.row - ROWSTRIDE);
            V3 e2p = vsub(s.p00, pm);
            V3 dp  = vsub(s.p01, pm);
            V3 cBp = vcross(e2p, dp);
            s.u2prev = vscale(cBp, rq(cBp));
        }

        const int nrows = min(ROWS, (G - 1) - r0);
        if (nrows == ROWS) {
            #pragma unroll 4
            for (int i = 0; i < ROWS; ++i) sum += quad_row(s);
        } else {
            for (int i = 0; i < nrows; ++i) sum += quad_row(s);
        }
    }

    // ---- block reduction ----
    #pragma unroll
    for (int off = 16; off > 0; off >>= 1)
        sum += __shfl_down_sync(0xFFFFFFFFu, sum, off);

    __shared__ float warp_sums[8];
    if (lane == 0) warp_sums[wid] = sum;
    __syncthreads();

    __shared__ bool is_last;
    if (wid == 0) {
        float sv = (lane < 8) ? warp_sums[lane] : 0.0f;
        #pragma unroll
        for (int off = 4; off > 0; off >>= 1)
            sv += __shfl_down_sync(0xFFFFFFFFu, sv, off);
        if (lane == 0) {
            atomicAdd(&g_acc, (double)sv);
            __threadfence();
            unsigned int done = atomicInc(&g_done, nblocks - 1);
            is_last = (done == nblocks - 1);
        }
    }
    __syncthreads();

    if (is_last && threadIdx.x == 0) {
        double acc = atomicAdd(&g_acc, 0.0);      // coherent read
        out[0] = (float)(1.0 - acc / N_TOTAL);    // loss = 1 - mean(cos)
        __threadfence();
        g_acc = 0.0;                               // g_done wrapped via atomicInc
    }
}

extern "C" void kernel_launch(void* const* d_in, const int* in_sizes, int n_in,
                              void* d_out, int out_size) {
    const float* x = (const float*)d_in[0];
    float* out = (float*)d_out;

    dim3 block(256, 1, 1);
    dim3 grid(NBLOCKS, 1, 1);   // 710 blocks -> one wave @ 5 CTA/SM
    nc_fused_kernel<<<grid, block>>>(x, out, NBLOCKS);
}